// round 7
// baseline (speedup 1.0000x reference)
#include <cuda_runtime.h>
#include <cstdint>

#define BATCH 16
#define CC 80
#define NN 16384              // locations per batch
#define NC (NN*CC)            // 1310720 candidates per batch
#define TOPN_ 1000
#define NBINS 8192            // histogram bins over [0.6, 1)
#define HLO 0.6f
#define SCALE ((float)NBINS / 0.4f)   // 20480
#define CAP1 131072           // stage-1 candidate capacity per batch (expected ~36K)
#define SORTN 2048            // smem sort capacity (expected ~1050 above cutoff)
#define QUADS_PER_BATCH (NC/4)        // 327680
#define LPB 128               // locations per block
#define BPB 128               // blocks per batch
#define NT 256                // threads per block
#define SBUF 1024             // per-block candidate buffer (expect ~290)
#define BINS_PT (NBINS/NT)    // 32 bins per thread in cutoff phase

// ------------------------- scratch (zero-initialized at module load; ---------
// ------------------------- self-cleaned by the tail phase every run) ---------
__device__ int    g_hist[BATCH*NBINS];
__device__ int    g_cnt1[BATCH];
__device__ int    g_done[BATCH];
__device__ unsigned long long g_cand1[(size_t)BATCH*CAP1];

__device__ __forceinline__ float sigmoidf_(float x){ return 1.0f/(1.0f + expf(-x)); }

struct PassS {
    float2 thr[LPB];                    // {ctr_sigmoid, xth}
    unsigned long long buf[SBUF];
};
struct FinalS {
    unsigned long long keys[SORTN];     // 16 KB
    float4 det[TOPN_];                  // 16 KB
    int    order[TOPN_];                // 4 KB
    int    S[NT];                       // 1 KB suffix sums
    int    ccnt[CC], coff[CC];
    int    wtot[8], wafter[8];
    unsigned char lab[TOPN_];
    unsigned char keep[TOPN_];
    int    g, cut, cnt, cnt1;
};

// One kernel does everything. 2048 blocks; each does pass1 for 128 whole
// locations; the LAST block to finish within a batch (threadfence+atomic
// ticket — no spinning, no deadlock) runs the per-batch final phase:
// cutoff-bin scan, gather, bitonic sort, decode, per-class NMS, output.
// Tail also re-zeroes this batch's hist/cnt/done so every graph replay
// starts from clean state (globals are zero-initialized at load).
__global__ void __launch_bounds__(NT)
k_all(const float* __restrict__ cls, const float* __restrict__ pctr,
      const float* __restrict__ boxes, const float* __restrict__ loc,
      float* __restrict__ out){
    __shared__ union { PassS a; FinalS f; } s;
    __shared__ int s_last;

    int b   = blockIdx.x >> 7;          // /BPB
    int blk = blockIdx.x & (BPB-1);
    int loc0 = blk * LPB;
    int tid = threadIdx.x, lane = tid & 31, wid = tid >> 5;

    // ================= PHASE A: pass1 over this block's 10240 cls values =====
    __shared__ int s_n, s_base;
    if (tid == 0) s_n = 0;
    if (tid < LPB){
        float sg = sigmoidf_(pctr[b*NN + loc0 + tid]);
        float xth = 3.3e38f;
        if (sg > HLO){
            float q = HLO / sg;                   // in (0.6, 1)
            xth = __logf(q/(1.0f-q)) - 1e-3f;     // conservative margin
        }
        s.a.thr[tid] = make_float2(sg, xth);
    }
    __syncthreads();

    const float4* p = reinterpret_cast<const float4*>(cls)
                    + (size_t)b*QUADS_PER_BATCH + (size_t)loc0*20;
    int* hist = g_hist + b*NBINS;

    #pragma unroll
    for (int hh = 0; hh < 2; hh++){
        float4 v[5];
        int    q[5];
        #pragma unroll
        for (int j = 0; j < 5; j++){
            q[j] = (hh*5 + j)*NT + tid;           // [0, 2560)
            v[j] = p[q[j]];
        }
        #pragma unroll
        for (int j = 0; j < 5; j++){
            float2 tc = s.a.thr[q[j]/20];         // x = ctr, y = xth
            float mx = fmaxf(fmaxf(v[j].x, v[j].y), fmaxf(v[j].z, v[j].w));
            if (mx > tc.y){                       // rare (~17% of quads)
                float xs[4] = {v[j].x, v[j].y, v[j].z, v[j].w};
                #pragma unroll
                for (int k = 0; k < 4; k++){
                    if (xs[k] > tc.y){
                        float s1 = sigmoidf_(xs[k]);
                        float sc = s1 * tc.x;
                        if (sc >= HLO){
                            unsigned idx = (unsigned)((loc0*20 + q[j])*4 + k);
                            int pos = atomicAdd(&s_n, 1);
                            if (pos < SBUF)
                                s.a.buf[pos] = ((unsigned long long)__float_as_uint(sc) << 21)
                                             | (unsigned long long)(0x1FFFFFu - idx);
                            int bin = (int)((sc - HLO) * SCALE);
                            if (bin > NBINS-1) bin = NBINS-1;
                            atomicAdd(&hist[bin], 1);
                        }
                    }
                }
            }
        }
    }
    __syncthreads();
    int n = s_n; if (n > SBUF) n = SBUF;
    if (tid == 0) s_base = atomicAdd(&g_cnt1[b], n);
    __syncthreads();
    int base = s_base;
    for (int i = tid; i < n; i += NT){
        int pos = base + i;
        if (pos < CAP1) g_cand1[(size_t)b*CAP1 + pos] = s.a.buf[i];
    }

    // ---- ticket: last block of this batch continues; others exit ----
    __syncthreads();
    __threadfence();
    if (tid == 0) s_last = (atomicAdd(&g_done[b], 1) == BPB-1);
    __syncthreads();
    if (!s_last) return;
    __threadfence();

    // ================= PHASE B: per-batch final (256 threads) ================
    // ---- B1: cutoff bin via suffix-sum over 8192-bin histogram ----
    int sacc = 0;
    #pragma unroll
    for (int k = 0; k < BINS_PT; k++) sacc += hist[tid*BINS_PT + k];
    int v = sacc;                                   // intra-warp inclusive suffix
    #pragma unroll
    for (int off = 1; off < 32; off <<= 1){
        int u = __shfl_down_sync(0xffffffffu, v, off);
        if (lane + off < 32) v += u;
    }
    if (lane == 0) s.f.wtot[wid] = v;
    if (tid == 0){ s.f.g = -1; s.f.cnt = 0; }
    __syncthreads();
    if (tid == 0){
        int acc = 0;
        for (int w = 7; w >= 0; w--){ s.f.wafter[w] = acc; acc += s.f.wtot[w]; }
    }
    __syncthreads();
    int T = v + s.f.wafter[wid];
    s.f.S[tid] = T;
    __syncthreads();
    if (T >= TOPN_ && (tid == NT-1 || s.f.S[tid+1] < TOPN_)) s.f.g = tid;
    __syncthreads();
    {
        int g = s.f.g;
        if (g >= 0 && tid == g){
            int cum = (g == NT-1) ? 0 : s.f.S[g+1];
            int bin = g*BINS_PT + BINS_PT-1;
            for (; bin >= g*BINS_PT; bin--){
                cum += hist[bin];
                if (cum >= TOPN_) break;
            }
            if (bin < g*BINS_PT) bin = g*BINS_PT;
            s.f.cut = bin;
        } else if (g < 0 && tid == 0) s.f.cut = 0;
        if (tid == 0){
            int c1 = g_cnt1[b]; if (c1 > CAP1) c1 = CAP1;
            s.f.cnt1 = c1;
        }
    }
    __syncthreads();
    int cut = s.f.cut;
    int cnt1 = s.f.cnt1;
    // self-clean this batch's state for the next graph replay
    #pragma unroll
    for (int k = 0; k < BINS_PT; k++) hist[tid*BINS_PT + k] = 0;
    if (tid == 0){ g_cnt1[b] = 0; g_done[b] = 0; }

    // ---- B2: gather candidates above cutoff into smem (batched loads) ----
    const unsigned long long* gc = g_cand1 + (size_t)b*CAP1;
    for (int i0 = 0; i0 < cnt1; i0 += NT*8){
        unsigned long long kk[8];
        #pragma unroll
        for (int r = 0; r < 8; r++){
            int i = i0 + r*NT + tid;
            kk[r] = (i < cnt1) ? gc[i] : 0ull;     // real keys are never 0
        }
        #pragma unroll
        for (int r = 0; r < 8; r++){
            if (kk[r]){
                float sc = __uint_as_float((unsigned)(kk[r] >> 21));
                int bin = (int)((sc - HLO) * SCALE);
                if (bin > NBINS-1) bin = NBINS-1;
                if (bin >= cut){
                    int pp = atomicAdd(&s.f.cnt, 1);
                    if (pp < SORTN) s.f.keys[pp] = kk[r];
                }
            }
        }
    }
    __syncthreads();
    int cnt = s.f.cnt; if (cnt > SORTN) cnt = SORTN;
    for (int i = tid; i < SORTN; i += NT)
        if (i >= cnt) s.f.keys[i] = 0ull;

    // ---- B3: bitonic sort 2048 keys descending (4 pairs per thread) ----
    for (int k = 2; k <= SORTN; k <<= 1){
        for (int j = k >> 1; j > 0; j >>= 1){
            __syncthreads();
            #pragma unroll
            for (int r = 0; r < 4; r++){
                int pid = tid + r*NT;               // pair id in [0, 1024)
                int idx = ((pid & ~(j-1)) << 1) | (pid & (j-1));
                int pr  = idx | j;
                unsigned long long a = s.f.keys[idx], c = s.f.keys[pr];
                bool up = (idx & k) == 0;
                if (up ? (a < c) : (a > c)){ s.f.keys[idx] = c; s.f.keys[pr] = a; }
            }
        }
    }
    __syncthreads();

    // ---- B4: decode top-1000 ----
    for (int i = tid; i < TOPN_; i += NT){
        unsigned long long key = s.f.keys[i];
        s.f.keep[i] = 0;
        if (key == 0ull){
            s.f.det[i] = make_float4(0.f,0.f,0.f,0.f);
            s.f.lab[i] = 0;
        } else {
            unsigned idx = 0x1FFFFFu - (unsigned)(key & 0x1FFFFFu);
            int nn2 = idx / CC, c = idx % CC;
            float4 pb = reinterpret_cast<const float4*>(boxes)[(size_t)b*NN + nn2];
            float2 l = reinterpret_cast<const float2*>(loc)[nn2];
            float x1 = fminf(fmaxf(l.x - pb.x, 0.0f), 1023.0f);
            float y1 = fminf(fmaxf(l.y - pb.y, 0.0f), 1023.0f);
            float x2 = fminf(fmaxf(l.x + pb.z, 0.0f), 1023.0f);
            float y2 = fminf(fmaxf(l.y + pb.w, 0.0f), 1023.0f);
            s.f.det[i] = make_float4(x1, y1, x2, y2);
            s.f.lab[i] = (unsigned char)(c + 1);
        }
    }
    if (tid < CC) s.f.ccnt[tid] = 0;
    __syncthreads();
    for (int i = tid; i < TOPN_; i += NT)
        if (s.f.lab[i]) atomicAdd(&s.f.ccnt[s.f.lab[i]-1], 1);
    __syncthreads();
    if (tid == 0){
        int acc = 0;
        for (int c = 0; c < CC; c++){ s.f.coff[c] = acc; acc += s.f.ccnt[c]; }
    }
    __syncthreads();

    // ---- B5: per-class greedy NMS (class offsets => cross-class IoU = 0) ----
    // 8 warps; 10 classes per warp. IoU on OFFSET boxes in reference op order.
    for (int c = wid; c < CC; c += 8){
        int off = s.f.coff[c];
        int m = 0;
        for (int k0 = 0; k0 < TOPN_; k0 += 32){
            int k = k0 + lane;
            bool match = (k < TOPN_) && (s.f.lab[k] == (unsigned char)(c+1));
            unsigned bal = __ballot_sync(0xffffffffu, match);
            if (match){
                int pos = m + __popc(bal & ((1u << lane) - 1u));
                s.f.order[off + pos] = k;       // ranks in descending-score order
            }
            m += __popc(bal);
        }
        float co = (float)(c+1) * 4096.0f;
        unsigned aliveM = 0xffffffffu;        // bit sl => entry e = sl*32+lane alive
        int Sl = (m + 31) >> 5;
        for (int i = 0; i < m; i++){
            int owner = i & 31, slot = i >> 5;
            unsigned a = __shfl_sync(0xffffffffu, aliveM, owner);
            if (!((a >> slot) & 1u)) continue;         // warp-uniform
            float4 bi = s.f.det[s.f.order[off + i]];
            bi.x += co; bi.y += co; bi.z += co; bi.w += co;
            float ai = fmaxf(bi.z - bi.x, 0.f) * fmaxf(bi.w - bi.y, 0.f);
            for (int s2 = 0; s2 < Sl; s2++){
                int e = (s2 << 5) + lane;
                if (e > i && e < m && ((aliveM >> s2) & 1u)){
                    float4 bj = s.f.det[s.f.order[off + e]];
                    bj.x += co; bj.y += co; bj.z += co; bj.w += co;
                    float aj = fmaxf(bj.z - bj.x, 0.f) * fmaxf(bj.w - bj.y, 0.f);
                    float ix1 = fmaxf(bi.x, bj.x), iy1 = fmaxf(bi.y, bj.y);
                    float ix2 = fminf(bi.z, bj.z), iy2 = fminf(bi.w, bj.w);
                    float inter = fmaxf(ix2 - ix1, 0.f) * fmaxf(iy2 - iy1, 0.f);
                    float iou = inter / ((ai + aj - inter) + 1e-9f);
                    if (iou > 0.6f) aliveM &= ~(1u << s2);
                }
            }
        }
        for (int s2 = 0; s2 < Sl; s2++){
            int e = (s2 << 5) + lane;
            if (e < m) s.f.keep[s.f.order[off + e]] = (unsigned char)((aliveM >> s2) & 1u);
        }
    }
    __syncthreads();

    // ---- B6: write output [boxes 16*1000*4][scores 16*1000][labels] ----
    for (int i = tid; i < TOPN_; i += NT){
        int t = b*TOPN_ + i;
        int kp = s.f.keep[i];
        float kf = kp ? 1.0f : 0.0f;
        float4 d = s.f.det[i];
        reinterpret_cast<float4*>(out)[t] =
            make_float4(d.x*kf, d.y*kf, d.z*kf, d.w*kf);
        unsigned long long key = s.f.keys[i];
        out[BATCH*TOPN_*4 + t] = kp ? __uint_as_float((unsigned)(key >> 21)) : 0.0f;
        out[BATCH*TOPN_*5 + t] = kp ? (float)s.f.lab[i] : 0.0f;
    }
}

// ------------------------- launch ---------------------------------------------
extern "C" void kernel_launch(void* const* d_in, const int* in_sizes, int n_in,
                              void* d_out, int out_size){
    const float* locations  = (const float*)d_in[0];
    const float* pred_cls   = (const float*)d_in[1];
    const float* pred_boxes = (const float*)d_in[2];
    const float* pred_ctr   = (const float*)d_in[3];
    float* out = (float*)d_out;

    k_all<<<BATCH*BPB, NT>>>(pred_cls, pred_ctr, pred_boxes, locations, out);
}

// round 8
// speedup vs baseline: 2.8199x; 2.8199x over previous
#include <cuda_runtime.h>
#include <cstdint>

#define BATCH 16
#define CC 80
#define NN 16384              // locations per batch
#define NC (NN*CC)            // 1310720 candidates per batch
#define TOPN_ 1000
#define NBINS 8192            // histogram bins over [0.6, 1)
#define HLO 0.6f
#define SCALE ((float)NBINS / 0.4f)   // 20480
#define CAP1 131072           // stage-1 candidate capacity per batch (expected ~36K)
#define SORTN 2048            // smem sort capacity (expected ~1050 above cutoff)
#define QUADS_PER_BATCH (NC/4)        // 327680
#define LPB 128               // locations per pass1 block
#define BPB 128               // pass1 blocks per batch
#define NT 256                // pass1 threads per block
#define NWARP 8
#define WBUF 192              // per-warp candidate buffer (expect ~36, 21-sigma margin)

// ------------------------- scratch (zero-initialized at module load; ---------
// ------------------------- self-cleaned by k_final every run) ----------------
__device__ int    g_hist[BATCH*NBINS];
__device__ int    g_cnt1[BATCH];
__device__ unsigned long long g_cand1[(size_t)BATCH*CAP1];

__device__ __forceinline__ float sigmoidf_(float x){ return 1.0f/(1.0f + expf(-x)); }

// ------------------------- single heavy pass over pred_cls --------------------
// Each block owns 128 whole locations (10240 cls elements): computes the
// per-location centerness sigmoid + conservative logit threshold into smem,
// then streams its cls quads (streaming loads, read-once): fmax-tree + 1
// compare fast path; exact sigmoid score only for survivors (~3%).
// Candidates go to PER-WARP smem buffers (distinct banks -> no cross-warp
// smem-atomic serialization), compacted with ONE global atomic per block.
// Key = (score_bits<<21) | (~idx & 21b) so descending sort == (value desc,
// index asc) — matches jax top_k tie order.
__global__ void __launch_bounds__(NT, 6)
k_pass1(const float* __restrict__ cls, const float* __restrict__ pctr){
    int b   = blockIdx.x >> 7;          // /BPB
    int blk = blockIdx.x & (BPB-1);
    int loc0 = blk * LPB;
    int tid = threadIdx.x, lane = tid & 31, wid = tid >> 5;

    __shared__ float2 s_thr[LPB];                       // {ctr_sigmoid, xth}
    __shared__ unsigned long long s_wbuf[NWARP][WBUF];  // 12 KB
    __shared__ int s_wn[NWARP];
    __shared__ int s_woff[NWARP];
    __shared__ int s_base;

    if (tid < NWARP) s_wn[tid] = 0;
    if (tid < LPB){
        float sg = sigmoidf_(pctr[b*NN + loc0 + tid]);
        float xth = 3.3e38f;
        if (sg > HLO){
            float q = HLO / sg;                   // in (0.6, 1)
            xth = __logf(q/(1.0f-q)) - 1e-3f;     // conservative margin
        }
        s_thr[tid] = make_float2(sg, xth);
    }
    __syncthreads();

    const float4* p = reinterpret_cast<const float4*>(cls)
                    + (size_t)b*QUADS_PER_BATCH + (size_t)loc0*20;
    int* hist = g_hist + b*NBINS;

    #pragma unroll
    for (int hh = 0; hh < 2; hh++){
        float4 v[5];
        #pragma unroll
        for (int j = 0; j < 5; j++)
            v[j] = __ldcs(&p[(hh*5 + j)*NT + tid]);     // streaming, read-once
        #pragma unroll
        for (int j = 0; j < 5; j++){
            int q = (hh*5 + j)*NT + tid;                // [0, 2560)
            float2 tc = s_thr[q/20];                    // x = ctr, y = xth
            float mx = fmaxf(fmaxf(v[j].x, v[j].y), fmaxf(v[j].z, v[j].w));
            if (mx > tc.y){                             // rare (~17% of quads)
                float xs[4] = {v[j].x, v[j].y, v[j].z, v[j].w};
                #pragma unroll
                for (int k = 0; k < 4; k++){
                    if (xs[k] > tc.y){
                        float s1 = sigmoidf_(xs[k]);
                        float sc = s1 * tc.x;
                        if (sc >= HLO){
                            unsigned idx = (unsigned)((loc0*20 + q)*4 + k);
                            int pos = atomicAdd(&s_wn[wid], 1);   // per-warp bank
                            if (pos < WBUF)
                                s_wbuf[wid][pos] =
                                    ((unsigned long long)__float_as_uint(sc) << 21)
                                  | (unsigned long long)(0x1FFFFFu - idx);
                            int bin = (int)((sc - HLO) * SCALE);
                            if (bin > NBINS-1) bin = NBINS-1;
                            atomicAdd(&hist[bin], 1);             // RED, scattered
                        }
                    }
                }
            }
        }
    }
    __syncthreads();
    if (tid == 0){
        int acc = 0;
        #pragma unroll
        for (int w = 0; w < NWARP; w++){
            int c = s_wn[w]; if (c > WBUF) c = WBUF;
            s_woff[w] = acc; acc += c;
        }
        s_base = atomicAdd(&g_cnt1[b], acc);
    }
    __syncthreads();
    {
        int wn = s_wn[wid]; if (wn > WBUF) wn = WBUF;
        int seg = s_base + s_woff[wid];
        for (int i = lane; i < wn; i += 32){
            int pos = seg + i;
            if (pos < CAP1) g_cand1[(size_t)b*CAP1 + pos] = s_wbuf[wid][i];
        }
    }
}

// ------------------------- fused: cutoff + gather + sort + decode + NMS + out -
// One block per batch. Everything smem-resident after the gather. Self-cleans
// this batch's hist/cnt so the next graph replay starts from zeroed state.
__global__ void __launch_bounds__(1024, 1)
k_final(const float* __restrict__ boxes, const float* __restrict__ loc,
        float* __restrict__ out){
    int b = blockIdx.x, tid = threadIdx.x, lane = tid & 31, wid = tid >> 5;

    __shared__ unsigned long long s_keys[SORTN];  // 16 KB
    __shared__ int   S[1024];                     // 4 KB (phase 1 only)
    __shared__ float4 s_det[TOPN_];               // 16 KB
    __shared__ unsigned char s_lab[TOPN_];        // 1 KB
    __shared__ unsigned char s_keep[TOPN_];       // 1 KB
    __shared__ int   s_order[TOPN_];              // 4 KB
    __shared__ int   s_ccnt[CC];
    __shared__ int   s_coff[CC];
    __shared__ int   s_wtot[32], s_wafter[32];
    __shared__ int   s_g, s_cut, s_cnt, s_cnt1;

    // ---- phase 1: find cutoff bin (suffix-sum over 8192-bin histogram) ----
    int* hist = g_hist + b*NBINS;
    int s = 0;
    #pragma unroll
    for (int k = 0; k < 8; k++) s += hist[tid*8 + k];
    int v = s;                                       // intra-warp inclusive suffix
    #pragma unroll
    for (int off = 1; off < 32; off <<= 1){
        int u = __shfl_down_sync(0xffffffffu, v, off);
        if (lane + off < 32) v += u;
    }
    if (lane == 0) s_wtot[wid] = v;
    if (tid == 0){
        s_g = -1; s_cnt = 0;
        int c1 = g_cnt1[b]; if (c1 > CAP1) c1 = CAP1;
        s_cnt1 = c1;
        g_cnt1[b] = 0;                               // self-clean
    }
    __syncthreads();
    if (wid == 0){
        int w = s_wtot[lane];
        int t2 = w;
        #pragma unroll
        for (int off = 1; off < 32; off <<= 1){
            int u = __shfl_down_sync(0xffffffffu, t2, off);
            if (lane + off < 32) t2 += u;
        }
        s_wafter[lane] = t2 - w;                     // sum over warps AFTER this one
    }
    __syncthreads();
    int T = v + s_wafter[wid];
    S[tid] = T;
    __syncthreads();
    if (T >= TOPN_ && (tid == 1023 || S[tid+1] < TOPN_)) s_g = tid;
    __syncthreads();
    if (tid == 0){
        int g = s_g, cut = 0;
        if (g >= 0){
            int cum = (g == 1023) ? 0 : S[g+1];
            int bin = g*8 + 7;
            for (; bin >= g*8; bin--){
                cum += hist[bin];
                if (cum >= TOPN_) break;
            }
            if (bin < g*8) bin = g*8;
            cut = bin;
        }
        s_cut = cut;
    }
    __syncthreads();
    int cut = s_cut;
    int cnt1 = s_cnt1;
    #pragma unroll
    for (int k = 0; k < 8; k++) hist[tid*8 + k] = 0; // self-clean histogram

    // ---- phase 2: gather candidates above cutoff into smem ----
    const unsigned long long* gc = g_cand1 + (size_t)b*CAP1;
    for (int i = tid; i < cnt1; i += 1024){
        unsigned long long key = gc[i];
        float sc = __uint_as_float((unsigned)(key >> 21));
        int bin = (int)((sc - HLO) * SCALE);
        if (bin > NBINS-1) bin = NBINS-1;
        if (bin >= cut){
            int p = atomicAdd(&s_cnt, 1);
            if (p < SORTN) s_keys[p] = key;
        }
    }
    __syncthreads();
    int cnt = s_cnt; if (cnt > SORTN) cnt = SORTN;
    for (int i = tid; i < SORTN; i += 1024)
        if (i >= cnt) s_keys[i] = 0ull;

    // ---- phase 3: bitonic sort 2048 keys descending (keys distinct) ----
    for (int k = 2; k <= SORTN; k <<= 1){
        for (int j = k >> 1; j > 0; j >>= 1){
            __syncthreads();
            int idx = ((tid & ~(j-1)) << 1) | (tid & (j-1));
            int pr  = idx | j;
            unsigned long long a = s_keys[idx], c = s_keys[pr];
            bool up = (idx & k) == 0;
            if (up ? (a < c) : (a > c)){ s_keys[idx] = c; s_keys[pr] = a; }
        }
    }
    __syncthreads();

    // ---- phase 4: decode top-1000 ----
    if (tid < TOPN_){
        unsigned long long key = s_keys[tid];
        s_keep[tid] = 0;
        if (key == 0ull){
            s_det[tid] = make_float4(0.f,0.f,0.f,0.f);
            s_lab[tid] = 0;
        } else {
            unsigned idx = 0x1FFFFFu - (unsigned)(key & 0x1FFFFFu);
            int n = idx / CC, c = idx % CC;
            float4 pb = reinterpret_cast<const float4*>(boxes)[(size_t)b*NN + n];
            float2 l = reinterpret_cast<const float2*>(loc)[n];
            float x1 = fminf(fmaxf(l.x - pb.x, 0.0f), 1023.0f);
            float y1 = fminf(fmaxf(l.y - pb.y, 0.0f), 1023.0f);
            float x2 = fminf(fmaxf(l.x + pb.z, 0.0f), 1023.0f);
            float y2 = fminf(fmaxf(l.y + pb.w, 0.0f), 1023.0f);
            s_det[tid] = make_float4(x1, y1, x2, y2);
            s_lab[tid] = (unsigned char)(c + 1);
        }
    }
    if (tid < CC) s_ccnt[tid] = 0;
    __syncthreads();
    if (tid < TOPN_ && s_lab[tid]) atomicAdd(&s_ccnt[s_lab[tid]-1], 1);
    __syncthreads();
    if (tid == 0){
        int acc = 0;
        for (int c = 0; c < CC; c++){ s_coff[c] = acc; acc += s_ccnt[c]; }
    }
    __syncthreads();

    // ---- phase 5: per-class greedy NMS (class offsets => cross-class IoU = 0) -
    // One warp per class; IoU computed on OFFSET boxes in reference op order.
    for (int c = wid; c < CC; c += 32){
        int off = s_coff[c];
        int m = 0;
        for (int k0 = 0; k0 < TOPN_; k0 += 32){
            int k = k0 + lane;
            bool match = (k < TOPN_) && (s_lab[k] == (unsigned char)(c+1));
            unsigned bal = __ballot_sync(0xffffffffu, match);
            if (match){
                int pos = m + __popc(bal & ((1u << lane) - 1u));
                s_order[off + pos] = k;       // ranks in descending-score order
            }
            m += __popc(bal);
        }
        float co = (float)(c+1) * 4096.0f;
        unsigned aliveM = 0xffffffffu;        // bit s2 => entry e = s2*32+lane alive
        int Sl = (m + 31) >> 5;
        for (int i = 0; i < m; i++){
            int owner = i & 31, slot = i >> 5;
            unsigned a = __shfl_sync(0xffffffffu, aliveM, owner);
            if (!((a >> slot) & 1u)) continue;         // warp-uniform
            float4 bi = s_det[s_order[off + i]];
            bi.x += co; bi.y += co; bi.z += co; bi.w += co;
            float ai = fmaxf(bi.z - bi.x, 0.f) * fmaxf(bi.w - bi.y, 0.f);
            for (int s2 = 0; s2 < Sl; s2++){
                int e = (s2 << 5) + lane;
                if (e > i && e < m && ((aliveM >> s2) & 1u)){
                    float4 bj = s_det[s_order[off + e]];
                    bj.x += co; bj.y += co; bj.z += co; bj.w += co;
                    float aj = fmaxf(bj.z - bj.x, 0.f) * fmaxf(bj.w - bj.y, 0.f);
                    float ix1 = fmaxf(bi.x, bj.x), iy1 = fmaxf(bi.y, bj.y);
                    float ix2 = fminf(bi.z, bj.z), iy2 = fminf(bi.w, bj.w);
                    float inter = fmaxf(ix2 - ix1, 0.f) * fmaxf(iy2 - iy1, 0.f);
                    float iou = inter / ((ai + aj - inter) + 1e-9f);
                    if (iou > 0.6f) aliveM &= ~(1u << s2);
                }
            }
        }
        for (int s2 = 0; s2 < Sl; s2++){
            int e = (s2 << 5) + lane;
            if (e < m) s_keep[s_order[off + e]] = (unsigned char)((aliveM >> s2) & 1u);
        }
    }
    __syncthreads();

    // ---- phase 6: write output [boxes 16*1000*4][scores 16*1000][labels] ----
    if (tid < TOPN_){
        int t = b*TOPN_ + tid;
        int kp = s_keep[tid];
        float kf = kp ? 1.0f : 0.0f;
        float4 d = s_det[tid];
        reinterpret_cast<float4*>(out)[t] =
            make_float4(d.x*kf, d.y*kf, d.z*kf, d.w*kf);
        unsigned long long key = s_keys[tid];
        out[BATCH*TOPN_*4 + t] = kp ? __uint_as_float((unsigned)(key >> 21)) : 0.0f;
        out[BATCH*TOPN_*5 + t] = kp ? (float)s_lab[tid] : 0.0f;
    }
}

// ------------------------- launch ---------------------------------------------
extern "C" void kernel_launch(void* const* d_in, const int* in_sizes, int n_in,
                              void* d_out, int out_size){
    const float* locations  = (const float*)d_in[0];
    const float* pred_cls   = (const float*)d_in[1];
    const float* pred_boxes = (const float*)d_in[2];
    const float* pred_ctr   = (const float*)d_in[3];
    float* out = (float*)d_out;

    k_pass1<<<BATCH*BPB, NT>>>(pred_cls, pred_ctr);
    k_final<<<BATCH, 1024>>>(pred_boxes, locations, out);
}